// round 17
// baseline (speedup 1.0000x reference)
#include <cuda_runtime.h>
#include <math.h>
#include <stdint.h>

#define HH 128
#define WW 128
#define BB 8
#define CIN 64
#define COUT 64
#define HW (HH*WW)
#define NCH 27            // 18 offset channels + 9 mask channels
#define NPAIR 7
#define CST2 132          // colT row stride in floats (128 + 4 pad)

// scratch (allocation-free: device globals)
__device__ float    g_om[BB*NCH*HW];   // offsets + mask=2*sigmoid
__device__ uint64_t g_wTd[9*64*64];    // [tap][cin][oc] : (w,w) dup pairs
__device__ int      g_flag[BB*64];     // per (b, row-pair) completion count

#define CONV_BLOCKS 512               // (32 hq) x (8 b) x (2 z), 4 rows each
#define DEF_BLOCKS  1024              // (8 b) x (128 h), full row per block
#define FSM_BYTES 43264               // max(conv 43264, deform colT 33792)

// ---------------------------------------------------------------------------
// packed fp32x2 helpers
// ---------------------------------------------------------------------------
__device__ __forceinline__ uint64_t pack2(float lo, float hi) {
    uint64_t r;
    asm("mov.b64 %0, {%1,%2};" : "=l"(r)
        : "r"(__float_as_uint(lo)), "r"(__float_as_uint(hi)));
    return r;
}
__device__ __forceinline__ void unpack2(uint64_t v, float& lo, float& hi) {
    uint32_t a, b;
    asm("mov.b64 {%0,%1}, %2;" : "=r"(a), "=r"(b) : "l"(v));
    lo = __uint_as_float(a); hi = __uint_as_float(b);
}
#define FFMA2(acc, a, b) \
    asm("fma.rn.f32x2 %0, %1, %2, %0;" : "+l"(acc) : "l"(a), "l"(b))

// ---------------------------------------------------------------------------
// Kernel 0: weight transform [oc][c][3][3] -> g_wTd[t][c][oc] = (w,w)
// ---------------------------------------------------------------------------
__global__ void transpose_w_kernel(const float* __restrict__ w) {
    int idx = blockIdx.x * 256 + threadIdx.x;
    if (idx < 576 * COUT) {
        int oc  = idx / 576;
        int rem = idx % 576;
        int c   = rem / 9;
        int t   = rem % 9;
        float v = w[idx];
        g_wTd[t * 4096 + c * 64 + oc] = pack2(v, v);
    }
}

// ---------------------------------------------------------------------------
// Conv role (R16 4-row body, unchanged).
// ---------------------------------------------------------------------------
__device__ __forceinline__ void conv_role(
    char* sm, int b, int c,
    const float* __restrict__ data,
    const float* __restrict__ w_off, const float* __restrict__ b_off,
    const float* __restrict__ w_mod, const float* __restrict__ b_mod)
{
    uint64_t* wsp   = (uint64_t*)sm;                 // 17920 B
    float*    dtile = (float*)(sm + 17920);          // 25344 B

    const int hq = c & 31;
    const int pb = (c >> 5) * NPAIR;                 // pair base (0 or 7)
    const int h0 = hq * 4;
    const int x  = threadIdx.x;

    if (threadIdx.x < 96) {
        int q = threadIdx.x / 12;
        int r = (threadIdx.x % 12) >> 1;
        int s = threadIdx.x & 1;
        dtile[q * 792 + r * 132 + s * 129] = 0.0f;
    }

    uint64_t acc2[4][NPAIR];
#pragma unroll
    for (int p = 0; p < NPAIR; p++) {
        int ocA = 2 * (pb + p), ocB = ocA + 1;
        float bA = (ocA < 18) ? b_off[ocA] : b_mod[ocA - 18];
        float bB = (ocB < 18) ? b_off[ocB] : ((ocB < 27) ? b_mod[ocB - 18] : 0.0f);
        acc2[0][p] = pack2(bA, bB);
        acc2[1][p] = acc2[0][p];
        acc2[2][p] = acc2[0][p];
        acc2[3][p] = acc2[0][p];
    }

    for (int c0 = 0; c0 < CIN; c0 += 32) {
        __syncthreads();
        for (int idx = threadIdx.x; idx < NPAIR * 32 * 9; idx += 128) {
            int p  = idx / 288;
            int r  = idx % 288;
            int cc = r / 9;
            int k  = r % 9;
            int ocA = 2 * (pb + p), ocB = ocA + 1;
            const float* sA = (ocA < 18) ? (w_off + ocA * 576) : (w_mod + (ocA - 18) * 576);
            float vA = sA[(c0 + cc) * 9 + k];
            float vB = 0.0f;
            if (ocB < 27) {
                const float* sB = (ocB < 18) ? (w_off + ocB * 576) : (w_mod + (ocB - 18) * 576);
                vB = sB[(c0 + cc) * 9 + k];
            }
            wsp[(p * 32 + cc) * 10 + k] = pack2(vA, vB);
        }

        for (int cg = 0; cg < 4; cg++) {
            __syncthreads();
            const int cb = c0 + cg * 8;
#pragma unroll
            for (int q = 0; q < 8; q++) {
                const float* dp = data + ((size_t)(b * CIN + cb + q)) * HW;
#pragma unroll
                for (int r = 0; r < 6; r++) {
                    int hy = h0 - 1 + r;
                    float v = 0.0f;
                    if (hy >= 0 && hy < HH) v = dp[hy * WW + x];
                    dtile[q * 792 + r * 132 + 1 + x] = v;
                }
            }
            __syncthreads();

#pragma unroll
            for (int q = 0; q < 8; q++) {
                const int cc = cg * 8 + q;
                const float* dp = dtile + q * 792 + x;
                uint64_t dup[6][3];
#pragma unroll
                for (int r = 0; r < 6; r++)
#pragma unroll
                    for (int kx = 0; kx < 3; kx++) {
                        float v = dp[r * 132 + kx];
                        dup[r][kx] = pack2(v, v);
                    }

#pragma unroll
                for (int p = 0; p < NPAIR; p++) {
                    const uint64_t* base = wsp + (p * 32 + cc) * 10;
                    ulonglong2 w01 = *(const ulonglong2*)(base + 0);
                    ulonglong2 w23 = *(const ulonglong2*)(base + 2);
                    ulonglong2 w45 = *(const ulonglong2*)(base + 4);
                    ulonglong2 w67 = *(const ulonglong2*)(base + 6);
                    uint64_t   w8  = base[8];
#pragma unroll
                    for (int rr = 0; rr < 4; rr++) {
                        FFMA2(acc2[rr][p], dup[rr + 0][0], w01.x);
                        FFMA2(acc2[rr][p], dup[rr + 0][1], w01.y);
                        FFMA2(acc2[rr][p], dup[rr + 0][2], w23.x);
                        FFMA2(acc2[rr][p], dup[rr + 1][0], w23.y);
                        FFMA2(acc2[rr][p], dup[rr + 1][1], w45.x);
                        FFMA2(acc2[rr][p], dup[rr + 1][2], w45.y);
                        FFMA2(acc2[rr][p], dup[rr + 2][0], w67.x);
                        FFMA2(acc2[rr][p], dup[rr + 2][1], w67.y);
                        FFMA2(acc2[rr][p], dup[rr + 2][2], w8);
                    }
                }
            }
        }
    }

#pragma unroll
    for (int rr = 0; rr < 4; rr++) {
        float* outp = g_om + ((size_t)(b * NCH) * HH + (h0 + rr)) * WW + x;
#pragma unroll
        for (int p = 0; p < NPAIR; p++) {
            float lo, hi;
            unpack2(acc2[rr][p], lo, hi);
            int ocA = 2 * (pb + p), ocB = ocA + 1;
            if (ocA >= 18) lo = 2.0f / (1.0f + expf(-lo));
            outp[ocA * HW] = lo;
            if (ocB < 27) {
                if (ocB >= 18) hi = 2.0f / (1.0f + expf(-hi));
                outp[ocB * HW] = hi;
            }
        }
    }

    __syncthreads();
    __threadfence();
    if (threadIdx.x == 0) {
        atomicAdd(&g_flag[b * 64 + hq * 2], 1);
        atomicAdd(&g_flag[b * 64 + hq * 2 + 1], 1);
    }
}

// ---------------------------------------------------------------------------
// Deform role: full 128-px row; acc packed over px-pairs (zero operand MOVs).
// Weights = pre-dup'd (w,w) u64 pairs read via broadcast LDG.128 from g_wTd
// (no wsm, no staging). smem = colT only (33792 B).
// ---------------------------------------------------------------------------
__device__ __forceinline__ void deform_role(
    char* sm, int b, int h,
    const float* __restrict__ data,
    const float* __restrict__ bias,
    float* __restrict__ out)
{
    float* colT = (float*)sm;                  // [64ch][CST2] 33792 B

    const int tid = threadIdx.x;

    // ---- wait for this row's offsets/masks ----
    if (tid == 0) {
        int* fp = &g_flag[b * 64 + (h >> 1)];
        while (atomicAdd(fp, 0) < 2) { __nanosleep(200); }
    }
    __syncthreads();
    __threadfence();

    const float* dbase = data + (size_t)b * CIN * HW;
    const float* omb   = g_om + ((size_t)(b * NCH) * HH + h) * WW;

    const int i   = tid >> 4;            // 0..7 -> oc base i*8
    const int j   = tid & 15;            // 0..15 -> px base j*4 (and 64+j*4)
    const int oc0 = i * 8;

    const int x = tid;                   // gather pixel = tid (0..127)

    uint64_t acc[8][4];                  // [oc][px pair]: pp0,pp1 = px j4..j4+3; pp2,pp3 = 64+j4..
#pragma unroll
    for (int o = 0; o < 8; o++)
#pragma unroll
        for (int q = 0; q < 4; q++) acc[o][q] = 0ULL;

    for (int t = 0; t < 9; t++) {
        __syncthreads();                 // prev GEMM done before overwrite

        // ---- bilinear metadata for this thread's pixel ----
        const float dy = omb[(2 * t) * HW + x];
        const float dx = omb[(2 * t + 1) * HW + x];
        const float mk = omb[(18 + t) * HW + x];

        const float py = (float)(h - 1 + t / 3) + dy;
        const float px = (float)(x - 1 + t % 3) + dx;

        const float y0f = floorf(py), x0f = floorf(px);
        const float wy1 = py - y0f,  wx1 = px - x0f;
        const float wy0 = 1.0f - wy1, wx0 = 1.0f - wx1;

        const int y0 = (int)y0f, x0 = (int)x0f;
        const int y1 = y0 + 1,   x1 = x0 + 1;
        const bool vy0 = (y0 >= 0) && (y0 < HH);
        const bool vy1 = (y1 >= 0) && (y1 < HH);
        const bool vx0 = (x0 >= 0) && (x0 < WW);
        const bool vx1 = (x1 >= 0) && (x1 < WW);

        const float w00 = (vy0 && vx0) ? mk * wy0 * wx0 : 0.0f;
        const float w01 = (vy0 && vx1) ? mk * wy0 * wx1 : 0.0f;
        const float w10 = (vy1 && vx0) ? mk * wy1 * wx0 : 0.0f;
        const float w11 = (vy1 && vx1) ? mk * wy1 * wx1 : 0.0f;

        const int yc0 = min(max(y0, 0), HH - 1);
        const int yc1 = min(max(y1, 0), HH - 1);
        const int xc0 = min(max(x0, 0), WW - 1);
        const int xc1 = min(max(x1, 0), WW - 1);
        const int i00 = yc0 * WW + xc0;
        const int i01 = yc0 * WW + xc1;
        const int i10 = yc1 * WW + xc0;
        const int i11 = yc1 * WW + xc1;

        // ---- gather all 64 channels for this pixel ----
        const float* d2 = dbase;
        float* cp = colT + x;
#pragma unroll 8
        for (int cc = 0; cc < 64; cc++) {
            float v = w00 * d2[i00];
            v = fmaf(w01, d2[i01], v);
            v = fmaf(w10, d2[i10], v);
            v = fmaf(w11, d2[i11], v);
            cp[cc * CST2] = v;
            d2 += HW;
        }
        __syncthreads();

        // ---- GEMM: 64 k; dup weights via broadcast LDG, px pairs native ----
        const uint64_t* wrow = g_wTd + t * 4096 + oc0;
        const float*    crow = colT + j * 4;
#pragma unroll 8
        for (int kl = 0; kl < 64; kl++) {
            ulonglong2 w01v = *(const ulonglong2*)(wrow + kl * 64);      // oc0,oc0+1
            ulonglong2 w23v = *(const ulonglong2*)(wrow + kl * 64 + 2);  // oc0+2,+3
            ulonglong2 w45v = *(const ulonglong2*)(wrow + kl * 64 + 4);  // oc0+4,+5
            ulonglong2 w67v = *(const ulonglong2*)(wrow + kl * 64 + 6);  // oc0+6,+7
            ulonglong2 ca = *(const ulonglong2*)(crow + kl * CST2);      // pp0, pp1
            ulonglong2 cb = *(const ulonglong2*)(crow + kl * CST2 + 64); // pp2, pp3
            FFMA2(acc[0][0], w01v.x, ca.x); FFMA2(acc[0][1], w01v.x, ca.y);
            FFMA2(acc[0][2], w01v.x, cb.x); FFMA2(acc[0][3], w01v.x, cb.y);
            FFMA2(acc[1][0], w01v.y, ca.x); FFMA2(acc[1][1], w01v.y, ca.y);
            FFMA2(acc[1][2], w01v.y, cb.x); FFMA2(acc[1][3], w01v.y, cb.y);
            FFMA2(acc[2][0], w23v.x, ca.x); FFMA2(acc[2][1], w23v.x, ca.y);
            FFMA2(acc[2][2], w23v.x, cb.x); FFMA2(acc[2][3], w23v.x, cb.y);
            FFMA2(acc[3][0], w23v.y, ca.x); FFMA2(acc[3][1], w23v.y, ca.y);
            FFMA2(acc[3][2], w23v.y, cb.x); FFMA2(acc[3][3], w23v.y, cb.y);
            FFMA2(acc[4][0], w45v.x, ca.x); FFMA2(acc[4][1], w45v.x, ca.y);
            FFMA2(acc[4][2], w45v.x, cb.x); FFMA2(acc[4][3], w45v.x, cb.y);
            FFMA2(acc[5][0], w45v.y, ca.x); FFMA2(acc[5][1], w45v.y, ca.y);
            FFMA2(acc[5][2], w45v.y, cb.x); FFMA2(acc[5][3], w45v.y, cb.y);
            FFMA2(acc[6][0], w67v.x, ca.x); FFMA2(acc[6][1], w67v.x, ca.y);
            FFMA2(acc[6][2], w67v.x, cb.x); FFMA2(acc[6][3], w67v.x, cb.y);
            FFMA2(acc[7][0], w67v.y, ca.x); FFMA2(acc[7][1], w67v.y, ca.y);
            FFMA2(acc[7][2], w67v.y, cb.x); FFMA2(acc[7][3], w67v.y, cb.y);
        }
    }

    // ---- epilogue: bias + relu + float4 stores ----
#pragma unroll
    for (int o = 0; o < 8; o++) {
        const int oc = oc0 + o;
        const float bb = bias[oc];
        float* ob = out + (((size_t)(b * COUT + oc)) * HH + h) * WW;
        float a0, a1, a2, a3;
        unpack2(acc[o][0], a0, a1);
        unpack2(acc[o][1], a2, a3);
        float4 rA = make_float4(fmaxf(a0 + bb, 0.f), fmaxf(a1 + bb, 0.f),
                                fmaxf(a2 + bb, 0.f), fmaxf(a3 + bb, 0.f));
        *(float4*)(ob + j * 4) = rA;
        unpack2(acc[o][2], a0, a1);
        unpack2(acc[o][3], a2, a3);
        float4 rB = make_float4(fmaxf(a0 + bb, 0.f), fmaxf(a1 + bb, 0.f),
                                fmaxf(a2 + bb, 0.f), fmaxf(a3 + bb, 0.f));
        *(float4*)(ob + 64 + j * 4) = rB;
    }
}

// ---------------------------------------------------------------------------
// Fused kernel: bids [0,512) conv (4-row), [512,1536) deform (full-row).
// ---------------------------------------------------------------------------
__global__ void __launch_bounds__(128, 4) fused_kernel4(
    const float* __restrict__ data,
    const float* __restrict__ w_off, const float* __restrict__ b_off,
    const float* __restrict__ w_mod, const float* __restrict__ b_mod,
    const float* __restrict__ bias,
    float* __restrict__ out)
{
    extern __shared__ char sm[];
    const int bid = blockIdx.x;
    if (bid < CONV_BLOCKS) {
        const int hq = bid & 31;
        const int b  = (bid >> 5) & 7;
        const int z  = bid >> 8;
        conv_role(sm, b, hq | (z << 5), data, w_off, b_off, w_mod, b_mod);
    } else {
        const int idx = bid - CONV_BLOCKS;
        deform_role(sm, idx >> 7, idx & 127, data, bias, out);
    }
}

// ---------------------------------------------------------------------------
extern "C" void kernel_launch(void* const* d_in, const int* in_sizes, int n_in,
                              void* d_out, int out_size)
{
    const float* data  = (const float*)d_in[0];
    const float* w     = (const float*)d_in[1];
    const float* bias  = (const float*)d_in[2];
    const float* w_off = (const float*)d_in[3];
    const float* b_off = (const float*)d_in[4];
    const float* w_mod = (const float*)d_in[5];
    const float* b_mod = (const float*)d_in[6];
    float* out = (float*)d_out;

    void* flag_ptr = nullptr;
    cudaGetSymbolAddress(&flag_ptr, g_flag);
    cudaMemsetAsync(flag_ptr, 0, BB * 64 * sizeof(int));

    cudaFuncSetAttribute(fused_kernel4,
                         cudaFuncAttributeMaxDynamicSharedMemorySize, FSM_BYTES);

    transpose_w_kernel<<<144, 256>>>(w);
    fused_kernel4<<<CONV_BLOCKS + DEF_BLOCKS, 128, FSM_BYTES>>>(
        data, w_off, b_off, w_mod, b_mod, bias, out);
}